// round 9
// baseline (speedup 1.0000x reference)
#include <cuda_runtime.h>
#include <cuda_bf16.h>

// BSplineActivation: y = sum_i B_i^3(clip(x,-1,1)) * c_i, uniform 12-knot
// grid, 8 coefficients. Per interval j (0..10) the spline is one cubic;
// bases+coefficients folded into an 11-entry cubic table re-centered at
// t=0.5 (magic-number round gives index bits + fractional offset s with only
// FADD/LOP3). Table lives in warp registers (lane l holds Q(l)); gather is
// 4x SHFL.IDX. Zero shared memory.
//
// R9: output stores are WRITE-THROUGH (__stwt). Theory: the plateau at
// ~12.8us across 7 structural variants is the LTS byte-throughput cap
// (~6300 B/cyc chip-wide). Default/.cs stores write-allocate in L2 and the
// dirty lines later write back to DRAM -> output bytes cross LTS twice.
// 33.5MB read + 2x33.5MB store-side = ~100MB / 6.9TB/s ~= the observed
// 13-14us. Write-through crosses LTS once: ~67MB -> ~9-10us predicted.

#define THREADS 256
#define VPT 4              // float4 per thread
#define MAGIC 12582912.0f  // 1.5 * 2^23

__global__ void __launch_bounds__(THREADS, 5)
bspline_act_kernel(const float* __restrict__ x,
                   const float* __restrict__ grid,
                   const float* __restrict__ coef,
                   float* __restrict__ out,
                   int n4)
{
    const int tid  = threadIdx.x;
    const int lane = tid & 31;

    const float4* __restrict__ x4 = (const float4*)x;
    float4* __restrict__ o4 = (float4*)out;

    const int base = blockIdx.x * (THREADS * VPT) + tid;

    // ---- Issue streaming input loads FIRST (overlap table-build latency) ----
    float4 v[VPT];
    #pragma unroll
    for (int q = 0; q < VPT; q++) {
        int i = base + q * THREADS;
        if (i < n4) v[q] = x4[i];
    }

    // ---- Per-lane table: lane l holds cubic Q(l) for interval l ----
    float q0, q1, q2, q3;
    {
        int j = lane < 11 ? lane : 10;
        int i0 = j - 3, i1 = j - 2, i2 = j - 1, i3 = j;
        float c0 = (i0 >= 0) ? __ldg(&coef[i0]) : 0.0f;   // i0 <= 7 always
        float c1 = (i1 >= 0) ? __ldg(&coef[i1]) : 0.0f;
        float c2 = (i2 >= 0 && i2 < 8) ? __ldg(&coef[i2]) : 0.0f;
        float c3 = (i3 < 8) ? __ldg(&coef[i3]) : 0.0f;
        float P0 = (c0 + 4.0f * c1 + c2) * (1.0f / 6.0f);
        float P1 = (c2 - c0) * 0.5f;
        float P2 = (c0 - 2.0f * c1 + c2) * 0.5f;
        float P3 = (c3 - c0 + 3.0f * (c1 - c2)) * (1.0f / 6.0f);
        // Re-center at t = s + 0.5, s in [-0.5, 0.5]
        q0 = P0 + 0.5f * P1 + 0.25f * P2 + 0.125f * P3;
        q1 = P1 + P2 + 0.75f * P3;
        q2 = P2 + 1.5f * P3;
        q3 = P3;
    }
    const float g0   = __ldg(&grid[0]);
    const float g11  = __ldg(&grid[11]);
    const float invh = 11.0f / (g11 - g0);
    const float cadd = -g0 * invh - 0.5f;

    #pragma unroll
    for (int q = 0; q < VPT; q++) {
        float4 r;
        #pragma unroll
        for (int k = 0; k < 4; k++) {
            float xv = (k == 0) ? v[q].x : (k == 1) ? v[q].y
                     : (k == 2) ? v[q].z : v[q].w;
            float xc = fminf(fmaxf(xv, -1.0f), 1.0f);
            float u  = fmaf(xc, invh, cadd);   // in [0.417, 9.583]
            float f  = u + MAGIC;
            float jf = f - MAGIC;              // round(u) = original floor
            float s  = u - jf;                 // in [-0.5, 0.5]
            int   j  = (int)(__float_as_uint(f) & 15u);
            float Q0 = __shfl_sync(0xffffffffu, q0, j);
            float Q1 = __shfl_sync(0xffffffffu, q1, j);
            float Q2 = __shfl_sync(0xffffffffu, q2, j);
            float Q3 = __shfl_sync(0xffffffffu, q3, j);
            float y  = fmaf(fmaf(fmaf(Q3, s, Q2), s, Q1), s, Q0);
            if (k == 0) r.x = y; else if (k == 1) r.y = y;
            else if (k == 2) r.z = y; else r.w = y;
        }
        int i = base + q * THREADS;
        if (i < n4) __stwt(&o4[i], r);   // write-through: no dirty writeback
    }
}

// Scalar tail kernel for n % 4 != 0 (not hit for 2048x4096).
__global__ void bspline_tail_kernel(const float* __restrict__ x,
                                    const float* __restrict__ grid,
                                    const float* __restrict__ coef,
                                    float* __restrict__ out,
                                    int start, int n)
{
    int idx = start + threadIdx.x;
    if (idx >= n) return;
    float g0  = grid[0];
    float invh = 11.0f / (grid[11] - g0);
    float xc = fminf(fmaxf(x[idx], -1.0f), 1.0f);
    float u  = (xc - g0) * invh;
    int   j  = min(max((int)u, 0), 10);
    float t  = u - (float)j;
    int i0 = j - 3, i1 = j - 2, i2 = j - 1, i3 = j;
    float c0 = (i0 >= 0 && i0 < 8) ? coef[i0] : 0.0f;
    float c1 = (i1 >= 0 && i1 < 8) ? coef[i1] : 0.0f;
    float c2 = (i2 >= 0 && i2 < 8) ? coef[i2] : 0.0f;
    float c3 = (i3 >= 0 && i3 < 8) ? coef[i3] : 0.0f;
    float p0 = (c0 + 4.0f * c1 + c2) * (1.0f / 6.0f);
    float p1 = (c2 - c0) * 0.5f;
    float p2 = (c0 - 2.0f * c1 + c2) * 0.5f;
    float p3 = (c3 - c0 + 3.0f * (c1 - c2)) * (1.0f / 6.0f);
    out[idx] = fmaf(fmaf(fmaf(p3, t, p2), t, p1), t, p0);
}

extern "C" void kernel_launch(void* const* d_in, const int* in_sizes, int n_in,
                              void* d_out, int out_size)
{
    const float* x    = (const float*)d_in[0];   // [2048*4096] fp32
    const float* grid = (const float*)d_in[1];   // [12] fp32
    const float* coef = (const float*)d_in[2];   // [8] fp32
    float* out = (float*)d_out;

    const int n  = in_sizes[0];
    const int n4 = n >> 2;

    int per_block = THREADS * VPT;
    int blocks = (n4 + per_block - 1) / per_block;
    if (blocks < 1) blocks = 1;

    bspline_act_kernel<<<blocks, THREADS>>>(x, grid, coef, out, n4);

    const int rem = n & 3;
    if (rem) {
        bspline_tail_kernel<<<1, 4>>>(x, grid, coef, out, n4 << 2, n);
    }
}

// round 10
// speedup vs baseline: 1.0226x; 1.0226x over previous
#include <cuda_runtime.h>
#include <cuda_bf16.h>
#include <cstdint>

// BSplineActivation: y = sum_i B_i^3(clip(x,-1,1)) * c_i, uniform 12-knot
// grid, 8 coefficients. Per interval j (0..10) the spline is one cubic;
// bases+coefficients folded into an 11-entry cubic table re-centered at
// t=0.5 (magic-number round -> index bits + fractional offset s, FADD/LOP3
// only). Table in warp registers (lane l holds Q(l)); gather = 4x SHFL.IDX.
//
// R10: TMA BULK STORES. Each block computes a contiguous 16KB output tile
// into SMEM, then one thread issues a single cp.async.bulk S2G. The DRAM
// write stream becomes 2048 sequential 16KB bursts (full-line, row-local)
// instead of 512B warp-STGs interleaved from ~740 CTAs. Stores leave via the
// async proxy, off the warp critical path.

#define THREADS 256
#define VPT 4                      // float4 per thread
#define TILE_F4 (THREADS * VPT)    // 1024 float4 = 16KB per block
#define TILE_BYTES (TILE_F4 * 16)
#define MAGIC 12582912.0f          // 1.5 * 2^23

__global__ void __launch_bounds__(THREADS, 5)
bspline_act_kernel(const float* __restrict__ x,
                   const float* __restrict__ grid,
                   const float* __restrict__ coef,
                   float* __restrict__ out,
                   int n4)
{
    __shared__ __align__(128) float4 sbuf[TILE_F4];   // 16KB output tile

    const int tid  = threadIdx.x;
    const int lane = tid & 31;

    const float4* __restrict__ x4 = (const float4*)x;
    float4* __restrict__ o4 = (float4*)out;

    const int tile0 = blockIdx.x * TILE_F4;
    const int base  = tile0 + tid;

    // ---- Front-batched streaming loads (4 independent LDG.128) ----
    float4 v[VPT];
    #pragma unroll
    for (int q = 0; q < VPT; q++) {
        int i = base + q * THREADS;
        if (i < n4) v[q] = x4[i];
    }

    // ---- Per-lane table: lane l holds cubic Q(l) for interval l ----
    float q0, q1, q2, q3;
    {
        int j = lane < 11 ? lane : 10;
        int i0 = j - 3, i1 = j - 2, i2 = j - 1, i3 = j;
        float c0 = (i0 >= 0) ? __ldg(&coef[i0]) : 0.0f;   // i0 <= 7 always
        float c1 = (i1 >= 0) ? __ldg(&coef[i1]) : 0.0f;
        float c2 = (i2 >= 0 && i2 < 8) ? __ldg(&coef[i2]) : 0.0f;
        float c3 = (i3 < 8) ? __ldg(&coef[i3]) : 0.0f;
        float P0 = (c0 + 4.0f * c1 + c2) * (1.0f / 6.0f);
        float P1 = (c2 - c0) * 0.5f;
        float P2 = (c0 - 2.0f * c1 + c2) * 0.5f;
        float P3 = (c3 - c0 + 3.0f * (c1 - c2)) * (1.0f / 6.0f);
        // Re-center at t = s + 0.5, s in [-0.5, 0.5]
        q0 = P0 + 0.5f * P1 + 0.25f * P2 + 0.125f * P3;
        q1 = P1 + P2 + 0.75f * P3;
        q2 = P2 + 1.5f * P3;
        q3 = P3;
    }
    const float g0   = __ldg(&grid[0]);
    const float g11  = __ldg(&grid[11]);
    const float invh = 11.0f / (g11 - g0);
    const float cadd = -g0 * invh - 0.5f;

    #pragma unroll
    for (int q = 0; q < VPT; q++) {
        float4 r;
        #pragma unroll
        for (int k = 0; k < 4; k++) {
            float xv = (k == 0) ? v[q].x : (k == 1) ? v[q].y
                     : (k == 2) ? v[q].z : v[q].w;
            float xc = fminf(fmaxf(xv, -1.0f), 1.0f);
            float u  = fmaf(xc, invh, cadd);   // in [0.417, 9.583]
            float f  = u + MAGIC;
            float jf = f - MAGIC;              // round(u) = original floor
            float s  = u - jf;                 // in [-0.5, 0.5]
            int   j  = (int)(__float_as_uint(f) & 15u);
            float Q0 = __shfl_sync(0xffffffffu, q0, j);
            float Q1 = __shfl_sync(0xffffffffu, q1, j);
            float Q2 = __shfl_sync(0xffffffffu, q2, j);
            float Q3 = __shfl_sync(0xffffffffu, q3, j);
            float y  = fmaf(fmaf(fmaf(Q3, s, Q2), s, Q1), s, Q0);
            if (k == 0) r.x = y; else if (k == 1) r.y = y;
            else if (k == 2) r.z = y; else r.w = y;
        }
        sbuf[tid + q * THREADS] = r;
    }
    __syncthreads();

    if (tile0 + TILE_F4 <= n4) {
        // Full tile: single 16KB TMA bulk store, sequential burst to DRAM.
        if (tid == 0) {
            asm volatile("fence.proxy.async.shared::cta;" ::: "memory");
            uint32_t saddr = (uint32_t)__cvta_generic_to_shared(sbuf);
            asm volatile(
                "cp.async.bulk.global.shared::cta.bulk_group [%0], [%1], %2;"
                :: "l"(o4 + tile0), "r"(saddr), "n"(TILE_BYTES)
                : "memory");
            asm volatile("cp.async.bulk.commit_group;" ::: "memory");
            asm volatile("cp.async.bulk.wait_group 0;" ::: "memory");
        }
    } else {
        // Partial tile (not hit for 2048x4096): plain stores.
        #pragma unroll
        for (int q = 0; q < VPT; q++) {
            int i = base + q * THREADS;
            if (i < n4) o4[i] = sbuf[tid + q * THREADS];
        }
    }
}

// Scalar tail kernel for n % 4 != 0 (not hit for 2048x4096).
__global__ void bspline_tail_kernel(const float* __restrict__ x,
                                    const float* __restrict__ grid,
                                    const float* __restrict__ coef,
                                    float* __restrict__ out,
                                    int start, int n)
{
    int idx = start + threadIdx.x;
    if (idx >= n) return;
    float g0  = grid[0];
    float invh = 11.0f / (grid[11] - g0);
    float xc = fminf(fmaxf(x[idx], -1.0f), 1.0f);
    float u  = (xc - g0) * invh;
    int   j  = min(max((int)u, 0), 10);
    float t  = u - (float)j;
    int i0 = j - 3, i1 = j - 2, i2 = j - 1, i3 = j;
    float c0 = (i0 >= 0 && i0 < 8) ? coef[i0] : 0.0f;
    float c1 = (i1 >= 0 && i1 < 8) ? coef[i1] : 0.0f;
    float c2 = (i2 >= 0 && i2 < 8) ? coef[i2] : 0.0f;
    float c3 = (i3 >= 0 && i3 < 8) ? coef[i3] : 0.0f;
    float p0 = (c0 + 4.0f * c1 + c2) * (1.0f / 6.0f);
    float p1 = (c2 - c0) * 0.5f;
    float p2 = (c0 - 2.0f * c1 + c2) * 0.5f;
    float p3 = (c3 - c0 + 3.0f * (c1 - c2)) * (1.0f / 6.0f);
    out[idx] = fmaf(fmaf(fmaf(p3, t, p2), t, p1), t, p0);
}

extern "C" void kernel_launch(void* const* d_in, const int* in_sizes, int n_in,
                              void* d_out, int out_size)
{
    const float* x    = (const float*)d_in[0];   // [2048*4096] fp32
    const float* grid = (const float*)d_in[1];   // [12] fp32
    const float* coef = (const float*)d_in[2];   // [8] fp32
    float* out = (float*)d_out;

    const int n  = in_sizes[0];
    const int n4 = n >> 2;

    int blocks = (n4 + TILE_F4 - 1) / TILE_F4;
    if (blocks < 1) blocks = 1;

    bspline_act_kernel<<<blocks, THREADS>>>(x, grid, coef, out, n4);

    const int rem = n & 3;
    if (rem) {
        bspline_tail_kernel<<<1, 4>>>(x, grid, coef, out, n4 << 2, n);
    }
}